// round 16
// baseline (speedup 1.0000x reference)
#include <cuda_runtime.h>
#include <cuda_bf16.h>
#include <math.h>

#define NODES   100000
#define EDGES   400000
#define EMB     300
#define HID     600
#define NGRAPH  4096
#define NLAYERS 5
#define CH4     75          // EMB/4
#define BN_EPS  1e-5f
#define INV_TEMP 25.0f      // 1/0.04

// k-pair row counts for split B images (8 * ceil(K/16))
#define ROWS_K300 152
#define ROWS_K600 304
#define W1IMG (ROWS_K300 * HID)      // 91200 per layer
#define W2IMG (ROWS_K600 * EMB)      // 91200 per layer
#define WPIMG (ROWS_K300 * EMB)      // 45600
#define F1IMG (ROWS_K300 * NGRAPH)   // 622592

// ------------------------- scratch (device globals; per-branch) -------------
__device__ float g_h   [2 * NODES * EMB];
__device__ float g_agg [2 * NODES * EMB];
__device__ float g_hid [2 * NODES * HID];
__device__ float g_f0  [NGRAPH * EMB];
__device__ float g_f1  [NGRAPH * EMB];
__device__ float g_pool[2 * NGRAPH * EMB];
__device__ float g_cnt [2 * NGRAPH];
__device__ float g_sum [2 * EMB];
__device__ float g_sqs [2 * EMB];
__device__ float g_zbias[NGRAPH];     // never written -> stays zero
// pre-split bf16 B images (hi/lo), loader-order layout [k-pair row][N]
__device__ unsigned g_w1s_h[NLAYERS * W1IMG];
__device__ unsigned g_w1s_l[NLAYERS * W1IMG];
__device__ unsigned g_w2s_h[NLAYERS * W2IMG];
__device__ unsigned g_w2s_l[NLAYERS * W2IMG];
__device__ unsigned g_wps_h[WPIMG];
__device__ unsigned g_wps_l[WPIMG];
__device__ unsigned g_f1s_h[F1IMG];
__device__ unsigned g_f1s_l[F1IMG];

// ------------------------- helpers ------------------------------------------
__device__ __forceinline__ void red4(float* p, float x, float y, float z, float w) {
    unsigned long long gp = __cvta_generic_to_global(p);
    asm volatile("red.global.add.v4.f32 [%0], {%1,%2,%3,%4};"
                 :: "l"(gp), "f"(x), "f"(y), "f"(z), "f"(w) : "memory");
}
__device__ __forceinline__ unsigned pack_bf16(float lo, float hi) {
    unsigned r;
    asm("cvt.rn.bf16x2.f32 %0, %1, %2;" : "=r"(r) : "f"(hi), "f"(lo));
    return r;
}
__device__ __forceinline__ float bf_lo(unsigned w) { return __uint_as_float(w << 16); }
__device__ __forceinline__ float bf_hi(unsigned w) { return __uint_as_float(w & 0xffff0000u); }

__device__ __forceinline__ void mma_bf16(float* c, const unsigned* a, const unsigned* b) {
    asm volatile(
        "mma.sync.aligned.m16n8k16.row.col.f32.bf16.bf16.f32 "
        "{%0,%1,%2,%3},{%4,%5,%6,%7},{%8,%9},{%0,%1,%2,%3};"
        : "+f"(c[0]), "+f"(c[1]), "+f"(c[2]), "+f"(c[3])
        : "r"(a[0]), "r"(a[1]), "r"(a[2]), "r"(a[3]), "r"(b[0]), "r"(b[1]));
}

// ------------------------- fused weight split prep ---------------------------
// image[kp*N + n] = pack(w[2kp][n], w[2kp+1][n]) hi/lo, zero-padded rows.
#define P_W1 (NLAYERS * W1IMG)
#define P_W2 (NLAYERS * W2IMG)
#define P_ALL (P_W1 + P_W2 + WPIMG)

__global__ void k_prep_all(const float* __restrict__ w1,
                           const float* __restrict__ w2,
                           const float* __restrict__ wp) {
    int idx = blockIdx.x * blockDim.x + threadIdx.x;
    if (idx >= P_ALL) return;
    const float* w; unsigned *ih, *il;
    int K, N, rem;
    if (idx < P_W1) {
        int l = idx / W1IMG; rem = idx % W1IMG;
        w = w1 + (size_t)l * EMB * HID; K = EMB; N = HID;
        ih = g_w1s_h + (size_t)l * W1IMG; il = g_w1s_l + (size_t)l * W1IMG;
    } else if (idx < P_W1 + P_W2) {
        int j = idx - P_W1;
        int l = j / W2IMG; rem = j % W2IMG;
        w = w2 + (size_t)l * HID * EMB; K = HID; N = EMB;
        ih = g_w2s_h + (size_t)l * W2IMG; il = g_w2s_l + (size_t)l * W2IMG;
    } else {
        rem = idx - P_W1 - P_W2;
        w = wp; K = EMB; N = EMB;
        ih = g_wps_h; il = g_wps_l;
    }
    int kp = rem / N, n = rem % N;
    int k0 = 2 * kp;
    float v0 = (k0 < K) ? w[(size_t)k0 * N + n] : 0.f;
    float v1 = (k0 + 1 < K) ? w[(size_t)(k0 + 1) * N + n] : 0.f;
    unsigned h = pack_bf16(v0, v1);
    ih[rem] = h;
    il[rem] = pack_bf16(v0 - bf_lo(h), v1 - bf_hi(h));
}

// transpose+split f1: img[kp*NGRAPH + n] = pack(f1[n][2kp], f1[n][2kp+1])
__global__ void k_transpose_f1() {
    int idx = blockIdx.x * blockDim.x + threadIdx.x;
    if (idx >= F1IMG) return;
    int kp = idx / NGRAPH, n = idx % NGRAPH;
    int k0 = 2 * kp;
    float v0 = (k0 < EMB) ? g_f1[(size_t)n * EMB + k0] : 0.f;
    float v1 = (k0 + 1 < EMB) ? g_f1[(size_t)n * EMB + k0 + 1] : 0.f;
    unsigned h = pack_bf16(v0, v1);
    g_f1s_h[idx] = h;
    g_f1s_l[idx] = pack_bf16(v0 - bf_lo(h), v1 - bf_hi(h));
}

// ------------------------- h init: h = ae1[x0]+ae2[x1]; agg = h + self0 -----
__global__ void k_init_h(const int* __restrict__ x,
                         const float* __restrict__ ae1,
                         const float* __restrict__ ae2,
                         const float* __restrict__ s1,
                         const float* __restrict__ s2,
                         float* __restrict__ h_, float* __restrict__ agg_) {
    int idx = blockIdx.x * blockDim.x + threadIdx.x;
    if (idx >= NODES * CH4) return;
    int node = idx / CH4, c = idx % CH4;
    int i0 = x[2 * node], i1 = x[2 * node + 1];
    float4 a = ((const float4*)ae1)[i0 * CH4 + c];
    float4 b = ((const float4*)ae2)[i1 * CH4 + c];
    float4 h = make_float4(a.x + b.x, a.y + b.y, a.z + b.z, a.w + b.w);
    ((float4*)h_)[idx] = h;
    float4 v1 = ((const float4*)s1)[c];
    float4 v2 = ((const float4*)s2)[c];
    ((float4*)agg_)[idx] = make_float4(h.x + v1.x + v2.x, h.y + v1.y + v2.y,
                                       h.z + v1.z + v2.z, h.w + v1.w + v2.w);
}

// ------------------------- edge scatter: agg[dst] += h[src] + eemb ----------
__global__ void k_edge_scatter(const int* __restrict__ ei,
                               const int* __restrict__ ea,
                               const float* __restrict__ ee1,
                               const float* __restrict__ ee2, int layer,
                               const float* __restrict__ h_,
                               float* __restrict__ agg_) {
    __shared__ __align__(16) float se1[6 * EMB];
    __shared__ __align__(16) float se2[3 * EMB];
    const float* t1 = ee1 + layer * 6 * EMB;
    const float* t2 = ee2 + layer * 3 * EMB;
    for (int i = threadIdx.x; i < 6 * EMB; i += blockDim.x) se1[i] = t1[i];
    for (int i = threadIdx.x; i < 3 * EMB; i += blockDim.x) se2[i] = t2[i];
    __syncthreads();

    int lane  = threadIdx.x & 31;
    int warp  = (blockIdx.x * blockDim.x + threadIdx.x) >> 5;
    int nwarp = (gridDim.x * blockDim.x) >> 5;
    const float4* h4  = (const float4*)h_;
    const float4* s14 = (const float4*)se1;
    const float4* s24 = (const float4*)se2;

    for (int e = warp; e < EDGES; e += nwarp) {
        int src = ei[e];
        int dst = ei[EDGES + e];
        int a0  = ea[2 * e];
        int a1  = ea[2 * e + 1];
        const float4* hs = h4 + (size_t)src * CH4;
        const float4* p1 = s14 + a0 * CH4;
        const float4* p2 = s24 + a1 * CH4;
        float* ad = agg_ + (size_t)dst * EMB;
        for (int c = lane; c < CH4; c += 32) {
            float4 hv = hs[c], v1 = p1[c], v2 = p2[c];
            red4(ad + 4 * c, hv.x + v1.x + v2.x, hv.y + v1.y + v2.y,
                             hv.z + v1.z + v2.z, hv.w + v1.w + v2.w);
        }
    }
}

// ------------------------- tensor-core GEMM (3x BF16 split) ------------------
// A: fp32, split in-loader.  B: pre-split hi/lo u32 images [k-pair row][N].
#define BM 128
#define BN 64
#define BK 16
#define ASTR 136
#define BSTR 72
#define ABUF (8 * ASTR)
#define BBUF (8 * BSTR)
#define SMEM_TC ((4 * ABUF + 4 * BBUF) * 4)

__global__ __launch_bounds__(256)
void k_gemm_tc(const float* __restrict__ A,
               const unsigned* __restrict__ B4h, const unsigned* __restrict__ B4l,
               const float* __restrict__ bias, float* __restrict__ C,
               int M, int N, int K, int doRelu) {
    extern __shared__ unsigned smu[];
    unsigned* Ah = smu;
    unsigned* Al = smu + 2 * ABUF;
    unsigned* Bh = smu + 4 * ABUF;
    unsigned* Bl = smu + 4 * ABUF + 2 * BBUF;

    int tid  = threadIdx.x;
    int lane = tid & 31;
    int warp = tid >> 5;
    int wm = warp >> 1;
    int wn = warp & 1;
    int g  = lane >> 2;
    int t  = lane & 3;
    int rowBase = blockIdx.y * BM;
    int colBase = blockIdx.x * BN;

    int af = tid & 3;
    int ar = tid >> 2;
    int bk2 = (tid & 127) >> 4;
    int bc  = (tid & 15) * 4;

    const int nk = (K + BK - 1) / BK;
    float acc[2][4][4] = {};
    float4 pa0, pa1;
    uint4 pbh, pbl;

    {
        int gk = 4 * af;
        bool kok = gk < K;
        int gr0 = rowBase + ar, gr1 = gr0 + 64;
        pa0 = make_float4(0, 0, 0, 0);
        pa1 = make_float4(0, 0, 0, 0);
        if (kok && gr0 < M) pa0 = *(const float4*)(A + (size_t)gr0 * K + gk);
        if (kok && gr1 < M) pa1 = *(const float4*)(A + (size_t)gr1 * K + gk);
        pbh = make_uint4(0, 0, 0, 0);
        pbl = make_uint4(0, 0, 0, 0);
        if (tid < 128) {
            int gc = colBase + bc;
            if (gc < N) {
                size_t off = (size_t)bk2 * N + gc;
                pbh = *(const uint4*)(B4h + off);
                pbl = *(const uint4*)(B4l + off);
            }
        }
    }
    int buf = 0;
    {
        const float* v0 = (const float*)&pa0;
        const float* v1 = (const float*)&pa1;
#pragma unroll
        for (int p = 0; p < 2; p++) {
            int kp = af * 2 + p;
            unsigned h0 = pack_bf16(v0[2 * p], v0[2 * p + 1]);
            unsigned h1 = pack_bf16(v1[2 * p], v1[2 * p + 1]);
            Ah[kp * ASTR + ar]      = h0;
            Ah[kp * ASTR + ar + 64] = h1;
            Al[kp * ASTR + ar]      = pack_bf16(v0[2*p] - bf_lo(h0), v0[2*p+1] - bf_hi(h0));
            Al[kp * ASTR + ar + 64] = pack_bf16(v1[2*p] - bf_lo(h1), v1[2*p+1] - bf_hi(h1));
        }
        if (tid < 128) {
            *(uint4*)&Bh[bk2 * BSTR + bc] = pbh;
            *(uint4*)&Bl[bk2 * BSTR + bc] = pbl;
        }
    }
    __syncthreads();

    for (int kt = 0; kt < nk; kt++) {
        if (kt + 1 < nk) {
            int k0t = (kt + 1) * BK;
            int gk = k0t + 4 * af;
            bool kok = gk < K;
            int gr0 = rowBase + ar, gr1 = gr0 + 64;
            pa0 = make_float4(0, 0, 0, 0);
            pa1 = make_float4(0, 0, 0, 0);
            if (kok && gr0 < M) pa0 = *(const float4*)(A + (size_t)gr0 * K + gk);
            if (kok && gr1 < M) pa1 = *(const float4*)(A + (size_t)gr1 * K + gk);
            pbh = make_uint4(0, 0, 0, 0);
            pbl = make_uint4(0, 0, 0, 0);
            if (tid < 128) {
                int gc = colBase + bc;
                if (gc < N) {
                    size_t off = (size_t)((kt + 1) * 8 + bk2) * N + gc;
                    pbh = *(const uint4*)(B4h + off);
                    pbl = *(const uint4*)(B4l + off);
                }
            }
        }
        {
            const unsigned* ah = Ah + buf * ABUF;
            const unsigned* al = Al + buf * ABUF;
            const unsigned* bh = Bh + buf * BBUF;
            const unsigned* bl = Bl + buf * BBUF;
            unsigned Afh[2][4], Afl[2][4];
#pragma unroll
            for (int i = 0; i < 2; i++) {
                int m = wm * 32 + i * 16 + g;
                Afh[i][0] = ah[t * ASTR + m];
                Afh[i][1] = ah[t * ASTR + m + 8];
                Afh[i][2] = ah[(t + 4) * ASTR + m];
                Afh[i][3] = ah[(t + 4) * ASTR + m + 8];
                Afl[i][0] = al[t * ASTR + m];
                Afl[i][1] = al[t * ASTR + m + 8];
                Afl[i][2] = al[(t + 4) * ASTR + m];
                Afl[i][3] = al[(t + 4) * ASTR + m + 8];
            }
            unsigned Bfh[4][2], Bfl[4][2];
#pragma unroll
            for (int j = 0; j < 4; j++) {
                int n = wn * 32 + j * 8 + g;
                Bfh[j][0] = bh[t * BSTR + n];
                Bfh[j][1] = bh[(t + 4) * BSTR + n];
                Bfl[j][0] = bl[t * BSTR + n];
                Bfl[j][1] = bl[(t + 4) * BSTR + n];
            }
#pragma unroll
            for (int i = 0; i < 2; i++)
#pragma unroll
                for (int j = 0; j < 4; j++) {
                    mma_bf16(acc[i][j], Afl[i], Bfh[j]);
                    mma_bf16(acc[i][j], Afh[i], Bfl[j]);
                    mma_bf16(acc[i][j], Afh[i], Bfh[j]);
                }
        }
        if (kt + 1 < nk) {
            buf ^= 1;
            unsigned* ahw = Ah + buf * ABUF;
            unsigned* alw = Al + buf * ABUF;
            unsigned* bhw = Bh + buf * BBUF;
            unsigned* blw = Bl + buf * BBUF;
            __syncthreads();
            const float* v0 = (const float*)&pa0;
            const float* v1 = (const float*)&pa1;
#pragma unroll
            for (int p = 0; p < 2; p++) {
                int kp = af * 2 + p;
                unsigned h0 = pack_bf16(v0[2 * p], v0[2 * p + 1]);
                unsigned h1 = pack_bf16(v1[2 * p], v1[2 * p + 1]);
                ahw[kp * ASTR + ar]      = h0;
                ahw[kp * ASTR + ar + 64] = h1;
                alw[kp * ASTR + ar]      = pack_bf16(v0[2*p] - bf_lo(h0), v0[2*p+1] - bf_hi(h0));
                alw[kp * ASTR + ar + 64] = pack_bf16(v1[2*p] - bf_lo(h1), v1[2*p+1] - bf_hi(h1));
            }
            if (tid < 128) {
                *(uint4*)&bhw[bk2 * BSTR + bc] = pbh;
                *(uint4*)&blw[bk2 * BSTR + bc] = pbl;
            }
            __syncthreads();
        }
    }

#pragma unroll
    for (int i = 0; i < 2; i++) {
#pragma unroll
        for (int j = 0; j < 4; j++) {
            int gc = colBase + wn * 32 + j * 8 + t * 2;
            if (gc >= N) continue;
            float b0 = bias[gc], b1 = bias[gc + 1];
            int gr0 = rowBase + wm * 32 + i * 16 + g;
            int gr1 = gr0 + 8;
            float o0 = acc[i][j][0] + b0, o1 = acc[i][j][1] + b1;
            float o2 = acc[i][j][2] + b0, o3 = acc[i][j][3] + b1;
            if (doRelu) {
                o0 = fmaxf(o0, 0.f); o1 = fmaxf(o1, 0.f);
                o2 = fmaxf(o2, 0.f); o3 = fmaxf(o3, 0.f);
            }
            if (gr0 < M) *(float2*)(C + (size_t)gr0 * N + gc) = make_float2(o0, o1);
            if (gr1 < M) *(float2*)(C + (size_t)gr1 * N + gc) = make_float2(o2, o3);
        }
    }
}

// ------------------------- batchnorm ---------------------------------------
__global__ void k_zero600(float* __restrict__ sum_, float* __restrict__ sqs_) {
    int t = threadIdx.x;
    if (t < EMB) { sum_[t] = 0.f; sqs_[t] = 0.f; }
}

__global__ void k_bn_reduce(const float* __restrict__ h_,
                            float* __restrict__ sum_, float* __restrict__ sqs_) {
    int c = threadIdx.x;
    if (c >= EMB) return;
    int base = blockIdx.x * 256;
    float s = 0.f, q = 0.f;
    for (int r = 0; r < 256; r++) {
        int row = base + r;
        if (row < NODES) {
            float v = h_[(size_t)row * EMB + c];
            s += v; q += v * v;
        }
    }
    atomicAdd(&sum_[c], s);
    atomicAdd(&sqs_[c], q);
}

__global__ void k_bn_norm(const float* __restrict__ gamma,
                          const float* __restrict__ beta,
                          const float* __restrict__ s1,
                          const float* __restrict__ s2, int doRelu,
                          float* __restrict__ h_, float* __restrict__ agg_,
                          const float* __restrict__ sum_,
                          const float* __restrict__ sqs_) {
    int idx = blockIdx.x * blockDim.x + threadIdx.x;
    if (idx >= NODES * CH4) return;
    int c = idx % CH4;
    const float invN = 1.f / (float)NODES;
    float4 v  = ((const float4*)h_)[idx];
    float4 s  = ((const float4*)sum_)[c];
    float4 q  = ((const float4*)sqs_)[c];
    float4 gm = ((const float4*)gamma)[c];
    float4 bt = ((const float4*)beta)[c];
    float m, var, is;
    m = s.x * invN; var = q.x * invN - m * m; is = rsqrtf(var + BN_EPS);
    v.x = (v.x - m) * is * gm.x + bt.x;
    m = s.y * invN; var = q.y * invN - m * m; is = rsqrtf(var + BN_EPS);
    v.y = (v.y - m) * is * gm.y + bt.y;
    m = s.z * invN; var = q.z * invN - m * m; is = rsqrtf(var + BN_EPS);
    v.z = (v.z - m) * is * gm.z + bt.z;
    m = s.w * invN; var = q.w * invN - m * m; is = rsqrtf(var + BN_EPS);
    v.w = (v.w - m) * is * gm.w + bt.w;
    if (doRelu) {
        v.x = fmaxf(v.x, 0.f); v.y = fmaxf(v.y, 0.f);
        v.z = fmaxf(v.z, 0.f); v.w = fmaxf(v.w, 0.f);
    }
    ((float4*)h_)[idx] = v;
    if (s1) {
        float4 v1 = ((const float4*)s1)[c];
        float4 v2 = ((const float4*)s2)[c];
        ((float4*)agg_)[idx] = make_float4(v.x + v1.x + v2.x, v.y + v1.y + v2.y,
                                           v.z + v1.z + v2.z, v.w + v1.w + v2.w);
    }
}

// ------------------------- pooling + normalize ------------------------------
__global__ void k_zero_pool(float* __restrict__ pool_, float* __restrict__ cnt_) {
    int idx = blockIdx.x * blockDim.x + threadIdx.x;
    if (idx < NGRAPH * EMB) pool_[idx] = 0.f;
    if (idx < NGRAPH) cnt_[idx] = 0.f;
}

__global__ void k_pool_scatter(const int* __restrict__ batch,
                               const float* __restrict__ proj_,
                               float* __restrict__ pool_) {
    int idx = blockIdx.x * blockDim.x + threadIdx.x;
    if (idx >= NODES * CH4) return;
    int node = idx / CH4, c = idx % CH4;
    int b = batch[node];
    float4 v = ((const float4*)proj_)[idx];
    red4(pool_ + (size_t)b * EMB + 4 * c, v.x, v.y, v.z, v.w);
}

__global__ void k_count(const int* __restrict__ batch, float* __restrict__ cnt_) {
    int i = blockIdx.x * blockDim.x + threadIdx.x;
    if (i < NODES) atomicAdd(&cnt_[batch[i]], 1.f);
}

__global__ void k_finalize(const float* __restrict__ pool_,
                           const float* __restrict__ cnt_,
                           float* __restrict__ fout, float scale) {
    int warp = (blockIdx.x * blockDim.x + threadIdx.x) >> 5;
    int lane = threadIdx.x & 31;
    if (warp >= NGRAPH) return;
    float ic = 1.f / fmaxf(cnt_[warp], 1.f);
    float sq = 0.f;
    for (int c = lane; c < EMB; c += 32) {
        float v = pool_[(size_t)warp * EMB + c] * ic;
        sq += v * v;
    }
#pragma unroll
    for (int o = 16; o > 0; o >>= 1) sq += __shfl_xor_sync(0xffffffffu, sq, o);
    float rn = scale / fmaxf(sqrtf(sq), 1e-12f);
    for (int c = lane; c < EMB; c += 32)
        fout[(size_t)warp * EMB + c] = pool_[(size_t)warp * EMB + c] * ic * rn;
}

// ------------------------- driver -------------------------------------------
extern "C" void kernel_launch(void* const* d_in, const int* in_sizes, int n_in,
                              void* d_out, int out_size) {
    (void)in_sizes; (void)n_in; (void)out_size;
    const int*   x[2]  = {(const int*)d_in[0], (const int*)d_in[4]};
    const int*   ei[2] = {(const int*)d_in[1], (const int*)d_in[5]};
    const int*   ea[2] = {(const int*)d_in[2], (const int*)d_in[6]};
    const int*   bt[2] = {(const int*)d_in[3], (const int*)d_in[7]};
    const float* ae1   = (const float*)d_in[8];
    const float* ae2   = (const float*)d_in[9];
    const float* ee1   = (const float*)d_in[10];
    const float* ee2   = (const float*)d_in[11];
    const float* w1    = (const float*)d_in[12];
    const float* b1    = (const float*)d_in[13];
    const float* w2    = (const float*)d_in[14];
    const float* b2    = (const float*)d_in[15];
    const float* gamma = (const float*)d_in[16];
    const float* beta  = (const float*)d_in[17];
    const float* pw    = (const float*)d_in[18];
    const float* pb    = (const float*)d_in[19];
    float* out = (float*)d_out;

    float *d_h0, *d_agg0, *d_hid0, *d_sum0, *d_sqs0, *d_pool0, *d_cnt0;
    float *d_f0, *d_f1, *d_zb;
    unsigned *d_w1h, *d_w1l, *d_w2h, *d_w2l, *d_wph, *d_wpl, *d_f1h, *d_f1l;
    cudaGetSymbolAddress((void**)&d_h0,   g_h);
    cudaGetSymbolAddress((void**)&d_agg0, g_agg);
    cudaGetSymbolAddress((void**)&d_hid0, g_hid);
    cudaGetSymbolAddress((void**)&d_sum0, g_sum);
    cudaGetSymbolAddress((void**)&d_sqs0, g_sqs);
    cudaGetSymbolAddress((void**)&d_pool0, g_pool);
    cudaGetSymbolAddress((void**)&d_cnt0, g_cnt);
    cudaGetSymbolAddress((void**)&d_f0, g_f0);
    cudaGetSymbolAddress((void**)&d_f1, g_f1);
    cudaGetSymbolAddress((void**)&d_zb, g_zbias);
    cudaGetSymbolAddress((void**)&d_w1h, g_w1s_h);
    cudaGetSymbolAddress((void**)&d_w1l, g_w1s_l);
    cudaGetSymbolAddress((void**)&d_w2h, g_w2s_h);
    cudaGetSymbolAddress((void**)&d_w2l, g_w2s_l);
    cudaGetSymbolAddress((void**)&d_wph, g_wps_h);
    cudaGetSymbolAddress((void**)&d_wpl, g_wps_l);
    cudaGetSymbolAddress((void**)&d_f1h, g_f1s_h);
    cudaGetSymbolAddress((void**)&d_f1l, g_f1s_l);

    static bool s_init = false;
    static cudaStream_t s_str[2];
    static cudaEvent_t s_evFork, s_evJoin[2];
    if (!s_init) {
        cudaStreamCreateWithFlags(&s_str[0], cudaStreamNonBlocking);
        cudaStreamCreateWithFlags(&s_str[1], cudaStreamNonBlocking);
        cudaEventCreateWithFlags(&s_evFork, cudaEventDisableTiming);
        cudaEventCreateWithFlags(&s_evJoin[0], cudaEventDisableTiming);
        cudaEventCreateWithFlags(&s_evJoin[1], cudaEventDisableTiming);
        s_init = true;
    }

    cudaFuncSetAttribute(k_gemm_tc, cudaFuncAttributeMaxDynamicSharedMemorySize,
                         SMEM_TC);

    const int NCH = NODES * CH4;
    dim3 grid1((HID + BN - 1) / BN, (NODES + BM - 1) / BM);
    dim3 grid2((EMB + BN - 1) / BN, (NODES + BM - 1) / BM);

    const float* selfs1[NLAYERS];
    const float* selfs2[NLAYERS];
    for (int l = 0; l < NLAYERS; l++) {
        selfs1[l] = ee1 + (size_t)(l * 6 + 4) * EMB;
        selfs2[l] = ee2 + (size_t)(l * 3 + 0) * EMB;
    }

    // pre-split all weight B operands (before the fork)
    k_prep_all<<<(P_ALL + 255) / 256, 256>>>(w1, w2, pw);

    // fork both branch streams from the capture (default) stream
    cudaEventRecord(s_evFork, 0);
    cudaStreamWaitEvent(s_str[0], s_evFork, 0);
    cudaStreamWaitEvent(s_str[1], s_evFork, 0);

    for (int br = 0; br < 2; br++) {
        cudaStream_t st = s_str[br];
        float* d_h    = d_h0    + (size_t)br * NODES * EMB;
        float* d_agg  = d_agg0  + (size_t)br * NODES * EMB;
        float* d_hid  = d_hid0  + (size_t)br * NODES * HID;
        float* d_sum  = d_sum0  + (size_t)br * EMB;
        float* d_sqs  = d_sqs0  + (size_t)br * EMB;
        float* d_pool = d_pool0 + (size_t)br * NGRAPH * EMB;
        float* d_cnt  = d_cnt0  + (size_t)br * NGRAPH;
        float* d_f    = br ? d_f1 : d_f0;

        k_init_h<<<(NCH + 255) / 256, 256, 0, st>>>(
            x[br], ae1, ae2, selfs1[0], selfs2[0], d_h, d_agg);
        for (int l = 0; l < NLAYERS; l++) {
            k_edge_scatter<<<2048, 256, 0, st>>>(ei[br], ea[br], ee1, ee2, l,
                                                 d_h, d_agg);
            k_gemm_tc<<<grid1, 256, SMEM_TC, st>>>(
                d_agg, d_w1h + (size_t)l * W1IMG, d_w1l + (size_t)l * W1IMG,
                b1 + (size_t)l * HID, d_hid, NODES, HID, EMB, 1);
            k_gemm_tc<<<grid2, 256, SMEM_TC, st>>>(
                d_hid, d_w2h + (size_t)l * W2IMG, d_w2l + (size_t)l * W2IMG,
                b2 + (size_t)l * EMB, d_h, NODES, EMB, HID, 0);
            k_zero600<<<1, 640, 0, st>>>(d_sum, d_sqs);
            k_bn_reduce<<<(NODES + 255) / 256, 320, 0, st>>>(d_h, d_sum, d_sqs);
            int last = (l == NLAYERS - 1);
            k_bn_norm<<<(NCH + 255) / 256, 256, 0, st>>>(
                gamma + (size_t)l * EMB, beta + (size_t)l * EMB,
                last ? nullptr : selfs1[l + 1], last ? nullptr : selfs2[l + 1],
                !last, d_h, d_agg, d_sum, d_sqs);
        }
        // projector: p = h @ pw + pb (into agg)
        k_gemm_tc<<<grid2, 256, SMEM_TC, st>>>(d_h, d_wph, d_wpl, pb, d_agg,
                                               NODES, EMB, EMB, 0);
        k_zero_pool<<<(NGRAPH * EMB + 255) / 256, 256, 0, st>>>(d_pool, d_cnt);
        k_pool_scatter<<<(NCH + 255) / 256, 256, 0, st>>>(bt[br], d_agg, d_pool);
        k_count<<<(NODES + 255) / 256, 256, 0, st>>>(bt[br], d_cnt);
        // branch 0 features carry the 1/TEMP scale so logits need no epilogue
        k_finalize<<<(NGRAPH * 32 + 255) / 256, 256, 0, st>>>(
            d_pool, d_cnt, d_f, br ? 1.f : INV_TEMP);
    }
    // transpose+split f1 on its own stream as soon as branch 1 finishes
    k_transpose_f1<<<(F1IMG + 255) / 256, 256, 0, s_str[1]>>>();

    // join back into the capture stream, then tensor-core logits
    cudaEventRecord(s_evJoin[0], s_str[0]);
    cudaEventRecord(s_evJoin[1], s_str[1]);
    cudaStreamWaitEvent(0, s_evJoin[0], 0);
    cudaStreamWaitEvent(0, s_evJoin[1], 0);
    // logits = (25*f0) [4096,300] @ f1t [300,4096] + 0
    k_gemm_tc<<<dim3(NGRAPH / BN, NGRAPH / BM), 256, SMEM_TC>>>(
        d_f0, d_f1h, d_f1l, d_zb, out, NGRAPH, NGRAPH, EMB, 0);
}

// round 17
// speedup vs baseline: 1.0491x; 1.0491x over previous
#include <cuda_runtime.h>
#include <cuda_bf16.h>
#include <math.h>

#define NODES   100000
#define EDGES   400000
#define EMB     300
#define HID     600
#define NGRAPH  4096
#define NLAYERS 5
#define CH4     75          // EMB/4
#define BN_EPS  1e-5f
#define INV_TEMP 25.0f      // 1/0.04

// ------------------------- scratch (device globals; per-branch) -------------
__device__ float g_h   [2 * NODES * EMB];
__device__ float g_agg [2 * NODES * EMB];
__device__ float g_hid [2 * NODES * HID];
__device__ float g_f0  [NGRAPH * EMB];
__device__ float g_f1  [NGRAPH * EMB];
__device__ float g_f1t [EMB * NGRAPH];
__device__ float g_pool[2 * NGRAPH * EMB];
__device__ float g_cnt [2 * NGRAPH];
__device__ float g_sum [2 * EMB];
__device__ float g_sqs [2 * EMB];
__device__ float g_zbias[NGRAPH];     // never written -> stays zero

// ------------------------- helpers ------------------------------------------
__device__ __forceinline__ void red4(float* p, float x, float y, float z, float w) {
    unsigned long long gp = __cvta_generic_to_global(p);
    asm volatile("red.global.add.v4.f32 [%0], {%1,%2,%3,%4};"
                 :: "l"(gp), "f"(x), "f"(y), "f"(z), "f"(w) : "memory");
}
__device__ __forceinline__ unsigned pack_bf16(float lo, float hi) {
    unsigned r;
    asm("cvt.rn.bf16x2.f32 %0, %1, %2;" : "=r"(r) : "f"(hi), "f"(lo));
    return r;
}
__device__ __forceinline__ float bf_lo(unsigned w) { return __uint_as_float(w << 16); }
__device__ __forceinline__ float bf_hi(unsigned w) { return __uint_as_float(w & 0xffff0000u); }

__device__ __forceinline__ void mma_bf16(float* c, const unsigned* a, const unsigned* b) {
    asm volatile(
        "mma.sync.aligned.m16n8k16.row.col.f32.bf16.bf16.f32 "
        "{%0,%1,%2,%3},{%4,%5,%6,%7},{%8,%9},{%0,%1,%2,%3};"
        : "+f"(c[0]), "+f"(c[1]), "+f"(c[2]), "+f"(c[3])
        : "r"(a[0]), "r"(a[1]), "r"(a[2]), "r"(a[3]), "r"(b[0]), "r"(b[1]));
}

// ------------------------- h init: h = ae1[x0]+ae2[x1]; agg = h + self0 -----
__global__ void k_init_h(const int* __restrict__ x,
                         const float* __restrict__ ae1,
                         const float* __restrict__ ae2,
                         const float* __restrict__ s1,
                         const float* __restrict__ s2,
                         float* __restrict__ h_, float* __restrict__ agg_) {
    int idx = blockIdx.x * blockDim.x + threadIdx.x;
    if (idx >= NODES * CH4) return;
    int node = idx / CH4, c = idx % CH4;
    int i0 = x[2 * node], i1 = x[2 * node + 1];
    float4 a = ((const float4*)ae1)[i0 * CH4 + c];
    float4 b = ((const float4*)ae2)[i1 * CH4 + c];
    float4 h = make_float4(a.x + b.x, a.y + b.y, a.z + b.z, a.w + b.w);
    ((float4*)h_)[idx] = h;
    float4 v1 = ((const float4*)s1)[c];
    float4 v2 = ((const float4*)s2)[c];
    ((float4*)agg_)[idx] = make_float4(h.x + v1.x + v2.x, h.y + v1.y + v2.y,
                                       h.z + v1.z + v2.z, h.w + v1.w + v2.w);
}

// ------------------------- edge scatter: agg[dst] += h[src] + eemb ----------
__global__ void k_edge_scatter(const int* __restrict__ ei,
                               const int* __restrict__ ea,
                               const float* __restrict__ ee1,
                               const float* __restrict__ ee2, int layer,
                               const float* __restrict__ h_,
                               float* __restrict__ agg_) {
    __shared__ __align__(16) float se1[6 * EMB];
    __shared__ __align__(16) float se2[3 * EMB];
    const float* t1 = ee1 + layer * 6 * EMB;
    const float* t2 = ee2 + layer * 3 * EMB;
    for (int i = threadIdx.x; i < 6 * EMB; i += blockDim.x) se1[i] = t1[i];
    for (int i = threadIdx.x; i < 3 * EMB; i += blockDim.x) se2[i] = t2[i];
    __syncthreads();

    int lane  = threadIdx.x & 31;
    int warp  = (blockIdx.x * blockDim.x + threadIdx.x) >> 5;
    int nwarp = (gridDim.x * blockDim.x) >> 5;
    const float4* h4  = (const float4*)h_;
    const float4* s14 = (const float4*)se1;
    const float4* s24 = (const float4*)se2;

    for (int e = warp; e < EDGES; e += nwarp) {
        int src = ei[e];
        int dst = ei[EDGES + e];
        int a0  = ea[2 * e];
        int a1  = ea[2 * e + 1];
        const float4* hs = h4 + (size_t)src * CH4;
        const float4* p1 = s14 + a0 * CH4;
        const float4* p2 = s24 + a1 * CH4;
        float* ad = agg_ + (size_t)dst * EMB;
        for (int c = lane; c < CH4; c += 32) {
            float4 hv = hs[c], v1 = p1[c], v2 = p2[c];
            red4(ad + 4 * c, hv.x + v1.x + v2.x, hv.y + v1.y + v2.y,
                             hv.z + v1.z + v2.z, hv.w + v1.w + v2.w);
        }
    }
}

// ------------------------- tensor-core GEMM (3x BF16 split) ------------------
#define BM 128
#define BN 64
#define BK 16
#define ASTR 136
#define BSTR 72
#define ABUF (8 * ASTR)
#define BBUF (8 * BSTR)
#define SMEM_TC ((4 * ABUF + 4 * BBUF) * 4)

__global__ __launch_bounds__(256)
void k_gemm_tc(const float* __restrict__ A, const float* __restrict__ B,
               const float* __restrict__ bias, float* __restrict__ C,
               int M, int N, int K, int doRelu) {
    extern __shared__ unsigned smu[];
    unsigned* Ah = smu;
    unsigned* Al = smu + 2 * ABUF;
    unsigned* Bh = smu + 4 * ABUF;
    unsigned* Bl = smu + 4 * ABUF + 2 * BBUF;

    int tid  = threadIdx.x;
    int lane = tid & 31;
    int warp = tid >> 5;
    int wm = warp >> 1;
    int wn = warp & 1;
    int g  = lane >> 2;
    int t  = lane & 3;
    int rowBase = blockIdx.y * BM;
    int colBase = blockIdx.x * BN;

    int af = tid & 3;
    int ar = tid >> 2;
    int bk2 = (tid & 127) >> 4;
    int bc  = (tid & 15) * 4;

    const int nk = (K + BK - 1) / BK;
    float acc[2][4][4] = {};
    float4 pa0, pa1, pb0, pb1;

    {
        int gk = 4 * af;
        bool kok = gk < K;
        int gr0 = rowBase + ar, gr1 = gr0 + 64;
        pa0 = make_float4(0, 0, 0, 0);
        pa1 = make_float4(0, 0, 0, 0);
        if (kok && gr0 < M) pa0 = *(const float4*)(A + (size_t)gr0 * K + gk);
        if (kok && gr1 < M) pa1 = *(const float4*)(A + (size_t)gr1 * K + gk);
        pb0 = make_float4(0, 0, 0, 0);
        pb1 = make_float4(0, 0, 0, 0);
        if (tid < 128) {
            int k0 = 2 * bk2, gc = colBase + bc;
            if (gc < N) {
                if (k0 < K)     pb0 = *(const float4*)(B + (size_t)k0 * N + gc);
                if (k0 + 1 < K) pb1 = *(const float4*)(B + (size_t)(k0 + 1) * N + gc);
            }
        }
    }
    int buf = 0;
    {
        const float* v0 = (const float*)&pa0;
        const float* v1 = (const float*)&pa1;
#pragma unroll
        for (int p = 0; p < 2; p++) {
            int kp = af * 2 + p;
            unsigned h0 = pack_bf16(v0[2 * p], v0[2 * p + 1]);
            unsigned h1 = pack_bf16(v1[2 * p], v1[2 * p + 1]);
            Ah[kp * ASTR + ar]      = h0;
            Ah[kp * ASTR + ar + 64] = h1;
            Al[kp * ASTR + ar]      = pack_bf16(v0[2*p] - bf_lo(h0), v0[2*p+1] - bf_hi(h0));
            Al[kp * ASTR + ar + 64] = pack_bf16(v1[2*p] - bf_lo(h1), v1[2*p+1] - bf_hi(h1));
        }
        if (tid < 128) {
            const float* b0 = (const float*)&pb0;
            const float* b1 = (const float*)&pb1;
#pragma unroll
            for (int i = 0; i < 4; i++) {
                unsigned h = pack_bf16(b0[i], b1[i]);
                Bh[bk2 * BSTR + bc + i] = h;
                Bl[bk2 * BSTR + bc + i] = pack_bf16(b0[i] - bf_lo(h), b1[i] - bf_hi(h));
            }
        }
    }
    __syncthreads();

    for (int kt = 0; kt < nk; kt++) {
        if (kt + 1 < nk) {
            int k0t = (kt + 1) * BK;
            int gk = k0t + 4 * af;
            bool kok = gk < K;
            int gr0 = rowBase + ar, gr1 = gr0 + 64;
            pa0 = make_float4(0, 0, 0, 0);
            pa1 = make_float4(0, 0, 0, 0);
            if (kok && gr0 < M) pa0 = *(const float4*)(A + (size_t)gr0 * K + gk);
            if (kok && gr1 < M) pa1 = *(const float4*)(A + (size_t)gr1 * K + gk);
            pb0 = make_float4(0, 0, 0, 0);
            pb1 = make_float4(0, 0, 0, 0);
            if (tid < 128) {
                int k0 = k0t + 2 * bk2, gc = colBase + bc;
                if (gc < N) {
                    if (k0 < K)     pb0 = *(const float4*)(B + (size_t)k0 * N + gc);
                    if (k0 + 1 < K) pb1 = *(const float4*)(B + (size_t)(k0 + 1) * N + gc);
                }
            }
        }
        {
            const unsigned* ah = Ah + buf * ABUF;
            const unsigned* al = Al + buf * ABUF;
            const unsigned* bh = Bh + buf * BBUF;
            const unsigned* bl = Bl + buf * BBUF;
            unsigned Afh[2][4], Afl[2][4];
#pragma unroll
            for (int i = 0; i < 2; i++) {
                int m = wm * 32 + i * 16 + g;
                Afh[i][0] = ah[t * ASTR + m];
                Afh[i][1] = ah[t * ASTR + m + 8];
                Afh[i][2] = ah[(t + 4) * ASTR + m];
                Afh[i][3] = ah[(t + 4) * ASTR + m + 8];
                Afl[i][0] = al[t * ASTR + m];
                Afl[i][1] = al[t * ASTR + m + 8];
                Afl[i][2] = al[(t + 4) * ASTR + m];
                Afl[i][3] = al[(t + 4) * ASTR + m + 8];
            }
            unsigned Bfh[4][2], Bfl[4][2];
#pragma unroll
            for (int j = 0; j < 4; j++) {
                int n = wn * 32 + j * 8 + g;
                Bfh[j][0] = bh[t * BSTR + n];
                Bfh[j][1] = bh[(t + 4) * BSTR + n];
                Bfl[j][0] = bl[t * BSTR + n];
                Bfl[j][1] = bl[(t + 4) * BSTR + n];
            }
            // term-major order: consecutive mmas hit distinct accumulators;
            // per-element accumulation order (lo*hi, hi*lo, hi*hi) unchanged.
#pragma unroll
            for (int i = 0; i < 2; i++)
#pragma unroll
                for (int j = 0; j < 4; j++)
                    mma_bf16(acc[i][j], Afl[i], Bfh[j]);
#pragma unroll
            for (int i = 0; i < 2; i++)
#pragma unroll
                for (int j = 0; j < 4; j++)
                    mma_bf16(acc[i][j], Afh[i], Bfl[j]);
#pragma unroll
            for (int i = 0; i < 2; i++)
#pragma unroll
                for (int j = 0; j < 4; j++)
                    mma_bf16(acc[i][j], Afh[i], Bfh[j]);
        }
        if (kt + 1 < nk) {
            buf ^= 1;
            unsigned* ahw = Ah + buf * ABUF;
            unsigned* alw = Al + buf * ABUF;
            unsigned* bhw = Bh + buf * BBUF;
            unsigned* blw = Bl + buf * BBUF;
            __syncthreads();
            const float* v0 = (const float*)&pa0;
            const float* v1 = (const float*)&pa1;
#pragma unroll
            for (int p = 0; p < 2; p++) {
                int kp = af * 2 + p;
                unsigned h0 = pack_bf16(v0[2 * p], v0[2 * p + 1]);
                unsigned h1 = pack_bf16(v1[2 * p], v1[2 * p + 1]);
                ahw[kp * ASTR + ar]      = h0;
                ahw[kp * ASTR + ar + 64] = h1;
                alw[kp * ASTR + ar]      = pack_bf16(v0[2*p] - bf_lo(h0), v0[2*p+1] - bf_hi(h0));
                alw[kp * ASTR + ar + 64] = pack_bf16(v1[2*p] - bf_lo(h1), v1[2*p+1] - bf_hi(h1));
            }
            if (tid < 128) {
                const float* b0 = (const float*)&pb0;
                const float* b1 = (const float*)&pb1;
#pragma unroll
                for (int i = 0; i < 4; i++) {
                    unsigned h = pack_bf16(b0[i], b1[i]);
                    bhw[bk2 * BSTR + bc + i] = h;
                    blw[bk2 * BSTR + bc + i] = pack_bf16(b0[i] - bf_lo(h), b1[i] - bf_hi(h));
                }
            }
            __syncthreads();
        }
    }

#pragma unroll
    for (int i = 0; i < 2; i++) {
#pragma unroll
        for (int j = 0; j < 4; j++) {
            int gc = colBase + wn * 32 + j * 8 + t * 2;
            if (gc >= N) continue;
            float b0 = bias[gc], b1 = bias[gc + 1];
            int gr0 = rowBase + wm * 32 + i * 16 + g;
            int gr1 = gr0 + 8;
            float o0 = acc[i][j][0] + b0, o1 = acc[i][j][1] + b1;
            float o2 = acc[i][j][2] + b0, o3 = acc[i][j][3] + b1;
            if (doRelu) {
                o0 = fmaxf(o0, 0.f); o1 = fmaxf(o1, 0.f);
                o2 = fmaxf(o2, 0.f); o3 = fmaxf(o3, 0.f);
            }
            if (gr0 < M) *(float2*)(C + (size_t)gr0 * N + gc) = make_float2(o0, o1);
            if (gr1 < M) *(float2*)(C + (size_t)gr1 * N + gc) = make_float2(o2, o3);
        }
    }
}

// ------------------------- batchnorm ---------------------------------------
__global__ void k_zero600(float* __restrict__ sum_, float* __restrict__ sqs_) {
    int t = threadIdx.x;
    if (t < EMB) { sum_[t] = 0.f; sqs_[t] = 0.f; }
}

__global__ void k_bn_reduce(const float* __restrict__ h_,
                            float* __restrict__ sum_, float* __restrict__ sqs_) {
    int c = threadIdx.x;
    if (c >= EMB) return;
    int base = blockIdx.x * 256;
    float s = 0.f, q = 0.f;
    for (int r = 0; r < 256; r++) {
        int row = base + r;
        if (row < NODES) {
            float v = h_[(size_t)row * EMB + c];
            s += v; q += v * v;
        }
    }
    atomicAdd(&sum_[c], s);
    atomicAdd(&sqs_[c], q);
}

__global__ void k_bn_norm(const float* __restrict__ gamma,
                          const float* __restrict__ beta,
                          const float* __restrict__ s1,
                          const float* __restrict__ s2, int doRelu,
                          float* __restrict__ h_, float* __restrict__ agg_,
                          const float* __restrict__ sum_,
                          const float* __restrict__ sqs_) {
    int idx = blockIdx.x * blockDim.x + threadIdx.x;
    if (idx >= NODES * CH4) return;
    int c = idx % CH4;
    const float invN = 1.f / (float)NODES;
    float4 v  = ((const float4*)h_)[idx];
    float4 s  = ((const float4*)sum_)[c];
    float4 q  = ((const float4*)sqs_)[c];
    float4 gm = ((const float4*)gamma)[c];
    float4 bt = ((const float4*)beta)[c];
    float m, var, is;
    m = s.x * invN; var = q.x * invN - m * m; is = rsqrtf(var + BN_EPS);
    v.x = (v.x - m) * is * gm.x + bt.x;
    m = s.y * invN; var = q.y * invN - m * m; is = rsqrtf(var + BN_EPS);
    v.y = (v.y - m) * is * gm.y + bt.y;
    m = s.z * invN; var = q.z * invN - m * m; is = rsqrtf(var + BN_EPS);
    v.z = (v.z - m) * is * gm.z + bt.z;
    m = s.w * invN; var = q.w * invN - m * m; is = rsqrtf(var + BN_EPS);
    v.w = (v.w - m) * is * gm.w + bt.w;
    if (doRelu) {
        v.x = fmaxf(v.x, 0.f); v.y = fmaxf(v.y, 0.f);
        v.z = fmaxf(v.z, 0.f); v.w = fmaxf(v.w, 0.f);
    }
    ((float4*)h_)[idx] = v;
    if (s1) {
        float4 v1 = ((const float4*)s1)[c];
        float4 v2 = ((const float4*)s2)[c];
        ((float4*)agg_)[idx] = make_float4(v.x + v1.x + v2.x, v.y + v1.y + v2.y,
                                           v.z + v1.z + v2.z, v.w + v1.w + v2.w);
    }
}

// ------------------------- pooling + normalize ------------------------------
__global__ void k_zero_pool(float* __restrict__ pool_, float* __restrict__ cnt_) {
    int idx = blockIdx.x * blockDim.x + threadIdx.x;
    if (idx < NGRAPH * EMB) pool_[idx] = 0.f;
    if (idx < NGRAPH) cnt_[idx] = 0.f;
}

__global__ void k_pool_scatter(const int* __restrict__ batch,
                               const float* __restrict__ proj_,
                               float* __restrict__ pool_) {
    int idx = blockIdx.x * blockDim.x + threadIdx.x;
    if (idx >= NODES * CH4) return;
    int node = idx / CH4, c = idx % CH4;
    int b = batch[node];
    float4 v = ((const float4*)proj_)[idx];
    red4(pool_ + (size_t)b * EMB + 4 * c, v.x, v.y, v.z, v.w);
}

__global__ void k_count(const int* __restrict__ batch, float* __restrict__ cnt_) {
    int i = blockIdx.x * blockDim.x + threadIdx.x;
    if (i < NODES) atomicAdd(&cnt_[batch[i]], 1.f);
}

__global__ void k_finalize(const float* __restrict__ pool_,
                           const float* __restrict__ cnt_,
                           float* __restrict__ fout, float scale) {
    int warp = (blockIdx.x * blockDim.x + threadIdx.x) >> 5;
    int lane = threadIdx.x & 31;
    if (warp >= NGRAPH) return;
    float ic = 1.f / fmaxf(cnt_[warp], 1.f);
    float sq = 0.f;
    for (int c = lane; c < EMB; c += 32) {
        float v = pool_[(size_t)warp * EMB + c] * ic;
        sq += v * v;
    }
#pragma unroll
    for (int o = 16; o > 0; o >>= 1) sq += __shfl_xor_sync(0xffffffffu, sq, o);
    float rn = scale / fmaxf(sqrtf(sq), 1e-12f);
    for (int c = lane; c < EMB; c += 32)
        fout[(size_t)warp * EMB + c] = pool_[(size_t)warp * EMB + c] * ic * rn;
}

// ------------------------- transpose f1 [NGRAPH,EMB] -> f1t [EMB,NGRAPH] -----
__global__ void k_transpose_f1() {
    int idx = blockIdx.x * blockDim.x + threadIdx.x;
    if (idx >= EMB * NGRAPH) return;
    int c = idx / NGRAPH, n = idx % NGRAPH;
    g_f1t[idx] = g_f1[(size_t)n * EMB + c];
}

// ------------------------- driver -------------------------------------------
extern "C" void kernel_launch(void* const* d_in, const int* in_sizes, int n_in,
                              void* d_out, int out_size) {
    (void)in_sizes; (void)n_in; (void)out_size;
    const int*   x[2]  = {(const int*)d_in[0], (const int*)d_in[4]};
    const int*   ei[2] = {(const int*)d_in[1], (const int*)d_in[5]};
    const int*   ea[2] = {(const int*)d_in[2], (const int*)d_in[6]};
    const int*   bt[2] = {(const int*)d_in[3], (const int*)d_in[7]};
    const float* ae1   = (const float*)d_in[8];
    const float* ae2   = (const float*)d_in[9];
    const float* ee1   = (const float*)d_in[10];
    const float* ee2   = (const float*)d_in[11];
    const float* w1    = (const float*)d_in[12];
    const float* b1    = (const float*)d_in[13];
    const float* w2    = (const float*)d_in[14];
    const float* b2    = (const float*)d_in[15];
    const float* gamma = (const float*)d_in[16];
    const float* beta  = (const float*)d_in[17];
    const float* pw    = (const float*)d_in[18];
    const float* pb    = (const float*)d_in[19];
    float* out = (float*)d_out;

    float *d_h0, *d_agg0, *d_hid0, *d_sum0, *d_sqs0, *d_pool0, *d_cnt0;
    float *d_f0, *d_f1, *d_f1t, *d_zb;
    cudaGetSymbolAddress((void**)&d_h0,   g_h);
    cudaGetSymbolAddress((void**)&d_agg0, g_agg);
    cudaGetSymbolAddress((void**)&d_hid0, g_hid);
    cudaGetSymbolAddress((void**)&d_sum0, g_sum);
    cudaGetSymbolAddress((void**)&d_sqs0, g_sqs);
    cudaGetSymbolAddress((void**)&d_pool0, g_pool);
    cudaGetSymbolAddress((void**)&d_cnt0, g_cnt);
    cudaGetSymbolAddress((void**)&d_f0, g_f0);
    cudaGetSymbolAddress((void**)&d_f1, g_f1);
    cudaGetSymbolAddress((void**)&d_f1t, g_f1t);
    cudaGetSymbolAddress((void**)&d_zb, g_zbias);

    static bool s_init = false;
    static cudaStream_t s_str[2];
    static cudaEvent_t s_evFork, s_evJoin[2];
    if (!s_init) {
        cudaStreamCreateWithFlags(&s_str[0], cudaStreamNonBlocking);
        cudaStreamCreateWithFlags(&s_str[1], cudaStreamNonBlocking);
        cudaEventCreateWithFlags(&s_evFork, cudaEventDisableTiming);
        cudaEventCreateWithFlags(&s_evJoin[0], cudaEventDisableTiming);
        cudaEventCreateWithFlags(&s_evJoin[1], cudaEventDisableTiming);
        s_init = true;
    }

    cudaFuncSetAttribute(k_gemm_tc, cudaFuncAttributeMaxDynamicSharedMemorySize,
                         SMEM_TC);

    const int NCH = NODES * CH4;
    dim3 grid1((HID + BN - 1) / BN, (NODES + BM - 1) / BM);
    dim3 grid2((EMB + BN - 1) / BN, (NODES + BM - 1) / BM);

    const float* selfs1[NLAYERS];
    const float* selfs2[NLAYERS];
    for (int l = 0; l < NLAYERS; l++) {
        selfs1[l] = ee1 + (size_t)(l * 6 + 4) * EMB;
        selfs2[l] = ee2 + (size_t)(l * 3 + 0) * EMB;
    }

    // fork both branch streams from the capture (default) stream
    cudaEventRecord(s_evFork, 0);
    cudaStreamWaitEvent(s_str[0], s_evFork, 0);
    cudaStreamWaitEvent(s_str[1], s_evFork, 0);

    for (int br = 0; br < 2; br++) {
        cudaStream_t st = s_str[br];
        float* d_h    = d_h0    + (size_t)br * NODES * EMB;
        float* d_agg  = d_agg0  + (size_t)br * NODES * EMB;
        float* d_hid  = d_hid0  + (size_t)br * NODES * HID;
        float* d_sum  = d_sum0  + (size_t)br * EMB;
        float* d_sqs  = d_sqs0  + (size_t)br * EMB;
        float* d_pool = d_pool0 + (size_t)br * NGRAPH * EMB;
        float* d_cnt  = d_cnt0  + (size_t)br * NGRAPH;
        float* d_f    = br ? d_f1 : d_f0;

        k_init_h<<<(NCH + 255) / 256, 256, 0, st>>>(
            x[br], ae1, ae2, selfs1[0], selfs2[0], d_h, d_agg);
        for (int l = 0; l < NLAYERS; l++) {
            k_edge_scatter<<<2048, 256, 0, st>>>(ei[br], ea[br], ee1, ee2, l,
                                                 d_h, d_agg);
            k_gemm_tc<<<grid1, 256, SMEM_TC, st>>>(
                d_agg, w1 + (size_t)l * EMB * HID,
                b1 + (size_t)l * HID, d_hid, NODES, HID, EMB, 1);
            k_gemm_tc<<<grid2, 256, SMEM_TC, st>>>(
                d_hid, w2 + (size_t)l * HID * EMB,
                b2 + (size_t)l * EMB, d_h, NODES, EMB, HID, 0);
            k_zero600<<<1, 640, 0, st>>>(d_sum, d_sqs);
            k_bn_reduce<<<(NODES + 255) / 256, 320, 0, st>>>(d_h, d_sum, d_sqs);
            int last = (l == NLAYERS - 1);
            k_bn_norm<<<(NCH + 255) / 256, 256, 0, st>>>(
                gamma + (size_t)l * EMB, beta + (size_t)l * EMB,
                last ? nullptr : selfs1[l + 1], last ? nullptr : selfs2[l + 1],
                !last, d_h, d_agg, d_sum, d_sqs);
        }
        // projector: p = h @ pw + pb (into agg)
        k_gemm_tc<<<grid2, 256, SMEM_TC, st>>>(d_h, pw, pb, d_agg,
                                               NODES, EMB, EMB, 0);
        k_zero_pool<<<(NGRAPH * EMB + 255) / 256, 256, 0, st>>>(d_pool, d_cnt);
        k_pool_scatter<<<(NCH + 255) / 256, 256, 0, st>>>(bt[br], d_agg, d_pool);
        k_count<<<(NODES + 255) / 256, 256, 0, st>>>(bt[br], d_cnt);
        // branch 0 features carry the 1/TEMP scale so logits need no epilogue
        k_finalize<<<(NGRAPH * 32 + 255) / 256, 256, 0, st>>>(
            d_pool, d_cnt, d_f, br ? 1.f : INV_TEMP);
    }
    // transpose f1 on its own stream as soon as branch 1 finishes
    k_transpose_f1<<<(EMB * NGRAPH + 255) / 256, 256, 0, s_str[1]>>>();

    // join back into the capture stream, then tensor-core logits
    cudaEventRecord(s_evJoin[0], s_str[0]);
    cudaEventRecord(s_evJoin[1], s_str[1]);
    cudaStreamWaitEvent(0, s_evJoin[0], 0);
    cudaStreamWaitEvent(0, s_evJoin[1], 0);
    // logits = (25*f0) [4096,300] @ f1t [300,4096] + 0
    k_gemm_tc<<<dim3(NGRAPH / BN, NGRAPH / BM), 256, SMEM_TC>>>(
        d_f0, d_f1t, d_zb, out, NGRAPH, NGRAPH, EMB, 0);
}